// round 11
// baseline (speedup 1.0000x reference)
#include <cuda_runtime.h>
#include <math.h>
#include <stdint.h>

#define HH 256
#define RN 512                 // B*V node rows
#define NH (RN*HH)             // node tensor elements
#define REDGE 131072           // B*V*V edge rows
#define EPS_BN 1e-5f

// node scratch slots
#define N_VSC 0
#define N_VST 1
#define N_WSC 2
#define N_WST 3
#define N_ABI 4
#define N_BBI 5
#define N_ASC 6
#define N_BSC 7
#define N_AST 8
#define N_BST 9

__device__ float g_node[10 * NH];
__device__ float g_acc_sc[NH];   // starts as Uh_sc, atomically accumulated
__device__ float g_acc_st[NH];   // starts as Uh_st
__device__ float g_esum[3 * HH];
__device__ float g_esq[3 * HH];
__device__ float g_escale[3 * HH];
__device__ float g_eshift[3 * HH];
__device__ float g_hsum[2 * HH];
__device__ float g_hsq[2 * HH];
__device__ float g_hscale[2 * HH];
__device__ float g_hshift[2 * HH];

// ------------------------------------------------------------------
// helpers
// ------------------------------------------------------------------
__device__ __forceinline__ uint32_t f2tf(float f) {
    uint32_t u;
    asm("cvt.rna.tf32.f32 %0, %1;" : "=r"(u) : "f"(f));
    return u;
}

__device__ __forceinline__ uint32_t smem_u32(const void* p) {
    uint32_t a;
    asm("{ .reg .u64 t; cvta.to.shared.u64 t, %1; cvt.u32.u64 %0, t; }"
        : "=r"(a) : "l"(p));
    return a;
}

__device__ __forceinline__ void cpa16(uint32_t dst, const void* src) {
    asm volatile("cp.async.cg.shared.global [%0], [%1], 16;"
                 :: "r"(dst), "l"(src) : "memory");
}
__device__ __forceinline__ void cpa_commit() {
    asm volatile("cp.async.commit_group;" ::: "memory");
}
template <int N>
__device__ __forceinline__ void cpa_wait() {
    asm volatile("cp.async.wait_group %0;" :: "n"(N) : "memory");
}

__device__ __forceinline__ void red2(float* p, float a, float b) {
    asm volatile("red.global.add.v2.f32 [%0], {%1, %2};"
                 :: "l"(p), "f"(a), "f"(b) : "memory");
}

__device__ __forceinline__ void mma8(float* d, const uint32_t* a, const uint32_t* b) {
    asm volatile(
        "mma.sync.aligned.m16n8k8.row.col.f32.tf32.tf32.f32 "
        "{%0,%1,%2,%3},{%4,%5,%6,%7},{%8,%9},{%0,%1,%2,%3};"
        : "+f"(d[0]), "+f"(d[1]), "+f"(d[2]), "+f"(d[3])
        : "r"(a[0]), "r"(a[1]), "r"(a[2]), "r"(a[3]), "r"(b[0]), "r"(b[1]));
}

__device__ __forceinline__ void ldsm4(uint32_t& r0, uint32_t& r1, uint32_t& r2,
                                      uint32_t& r3, uint32_t addr) {
    asm volatile("ldmatrix.sync.aligned.m8n8.x4.shared.b16 {%0,%1,%2,%3}, [%4];"
                 : "=r"(r0), "=r"(r1), "=r"(r2), "=r"(r3) : "r"(addr));
}

// ==================================================================
// Edge GEMM: e2[row, ch] = X[row,:]·W[ch,:] + bias + Ah_i + Bh_j, fused
// sigmoid-gate aggregation + BN statistics.
// CTA tile: 128 rows x 128 channels, K=256 in 8 chunks of 32.
// 512 threads: 16 warps (4M x 4N), warp tile 32x32. 3-stage cp.async
// pipeline, ldmatrix fragment loads, raw fp32 bits into tf32 mma (RZ).
// 2 CTAs/SM -> 32 warps/SM (reg cap 64 via launch bounds).
// Epilogue is fully coalesced via an smem accumulator transpose.
// MODE: 1 = bi edge, 2 = sc edge, 3 = st edge
// ==================================================================
#define SM_CHUNK 16384                 // one operand tile: 128 rows * 128B
#define SM_BUF   (2 * SM_CHUNK)        // A + B tiles per stage (32KB)
#define SM_TOTAL (3 * SM_BUF)          // 3 stages = 96KB
#define TPITCH   132                   // padded fp32 pitch for transpose
#define SRED_OFF (128 * TPITCH)        // float offset of stats scratch

template <int MODE>
__global__ void __launch_bounds__(512, 2) edge_gemm(
    const float* __restrict__ X, const float* __restrict__ W,
    const float* __restrict__ bias, float* __restrict__ Y)
{
    extern __shared__ char smem[];
    const uint32_t sbase = smem_u32(smem);

    const int tid  = threadIdx.x;
    const int lane = tid & 31;
    const int warp = tid >> 5;
    const int wm = warp & 3;       // 4 warps along M (32 rows each)
    const int wn = warp >> 2;      // 4 warps along N (32 cols each)
    const int g = lane >> 2;
    const int t = lane & 3;
    const int rowBase = blockIdx.y * 128;
    const int colBase = blockIdx.x * 128;

    const int lr = tid >> 3;       // 0..63
    const int lf = tid & 7;        // float4 index within 32-float k-row

    // ldmatrix per-thread addressing invariants
    const int mlo = (lane >> 3) & 1;   // matrix pair low bit
    const int mhi = lane >> 4;         // matrix pair high bit
    const int rl  = lane & 7;          // row within matrix

    uint32_t aoffm[2]; int a7[2];
#pragma unroll
    for (int mt = 0; mt < 2; mt++) {
        const int row = wm * 32 + mt * 16 + mlo * 8 + rl;
        aoffm[mt] = (uint32_t)row * 128;
        a7[mt] = row & 7;
    }
    uint32_t boffm[2]; int b7[2];
#pragma unroll
    for (int ntp = 0; ntp < 2; ntp++) {
        const int nrow = wn * 32 + (2 * ntp + mhi) * 8 + rl;
        boffm[ntp] = (uint32_t)(SM_CHUNK + nrow * 128);
        b7[ntp] = nrow & 7;
    }

    float acc[2][4][4];
#pragma unroll
    for (int a = 0; a < 2; a++)
#pragma unroll
        for (int b = 0; b < 4; b++)
#pragma unroll
            for (int c = 0; c < 4; c++) acc[a][b][c] = 0.f;

    // ---- staging helper (cp.async, swizzled 16B), 512 threads ----
    auto stage = [&](int buf, int k0) {
        const uint32_t boff = sbase + buf * SM_BUF;
#pragma unroll
        for (int ii = 0; ii < 2; ii++) {
            const int r = lr + 64 * ii;
            const uint32_t sw = (uint32_t)((lf ^ (r & 7)) << 4);
            cpa16(boff + r * 128 + sw,
                  X + (size_t)(rowBase + r) * HH + k0 + lf * 4);
            cpa16(boff + SM_CHUNK + r * 128 + sw,
                  W + (size_t)(colBase + r) * HH + k0 + lf * 4);
        }
    };

    stage(0, 0);  cpa_commit();
    stage(1, 32); cpa_commit();

    for (int c = 0; c < 8; c++) {
        if (c < 7) cpa_wait<1>(); else cpa_wait<0>();
        __syncthreads();
        if (c < 6) { stage((c + 2) % 3, (c + 2) * 32); cpa_commit(); }

        const uint32_t sb = sbase + (c % 3) * SM_BUF;

#pragma unroll
        for (int ks = 0; ks < 4; ks++) {
            uint32_t af[2][4];
#pragma unroll
            for (int mt = 0; mt < 2; mt++) {
                const uint32_t addr = sb + aoffm[mt] +
                    (uint32_t)(((2 * ks + mhi) ^ a7[mt]) << 4);
                ldsm4(af[mt][0], af[mt][1], af[mt][2], af[mt][3], addr);
            }
            uint32_t bf[2][4];
#pragma unroll
            for (int ntp = 0; ntp < 2; ntp++) {
                const uint32_t addr = sb + boffm[ntp] +
                    (uint32_t)(((2 * ks + mlo) ^ b7[ntp]) << 4);
                ldsm4(bf[ntp][0], bf[ntp][1], bf[ntp][2], bf[ntp][3], addr);
            }
#pragma unroll
            for (int ntp = 0; ntp < 2; ntp++)
#pragma unroll
                for (int mt = 0; mt < 2; mt++) {
                    mma8(acc[mt][2 * ntp],     af[mt], &bf[ntp][0]);
                    mma8(acc[mt][2 * ntp + 1], af[mt], &bf[ntp][2]);
                }
        }
    }
    __syncthreads();   // mainloop smem no longer needed

    // ---------------- fused epilogue (coalesced via smem transpose) ----------
    constexpr bool HAS_ROW = (MODE == 1) || (MODE == 2);  // sum over j -> acc[b,i]
    constexpr bool HAS_COL = (MODE == 1) || (MODE == 3);  // sum over i -> acc[b,j]

    const float* rowA; const float* rowB;
    const float* VjB = nullptr; const float* ViB = nullptr;
    float* accRow = nullptr; float* accCol = nullptr;
    float* esum; float* esq;
    if (MODE == 1) {
        rowA = g_node + (size_t)N_ABI * NH; rowB = g_node + (size_t)N_BBI * NH;
        VjB = g_node + (size_t)N_VST * NH;  ViB = g_node + (size_t)N_VSC * NH;
        accRow = g_acc_sc; accCol = g_acc_st;
        esum = g_esum; esq = g_esq;
    } else if (MODE == 2) {
        rowA = g_node + (size_t)N_ASC * NH; rowB = g_node + (size_t)N_BSC * NH;
        VjB = g_node + (size_t)N_WSC * NH;
        accRow = g_acc_sc;
        esum = g_esum + HH; esq = g_esq + HH;
    } else {
        rowA = g_node + (size_t)N_AST * NH; rowB = g_node + (size_t)N_BST * NH;
        ViB = g_node + (size_t)N_WST * NH;
        accCol = g_acc_st;
        esum = g_esum + 2 * HH; esq = g_esq + 2 * HH;
    }

    const int biIdx = rowBase >> 8;         // b*V + i (128-row block sits in one i)
    const int bbase = (rowBase >> 16) << 8; // b*V
    const int jbase = rowBase & 255;

    float* sT = reinterpret_cast<float*>(smem);          // [128][TPITCH]
    float* s_red = sT + SRED_OFF;                        // 384 floats

    // dump accumulators to smem (mma layout) + zero stats scratch
    for (int i = tid; i < 384; i += 512) s_red[i] = 0.f;
#pragma unroll
    for (int nt = 0; nt < 4; nt++) {
        const int col = wn * 32 + nt * 8 + t * 2;
#pragma unroll
        for (int mt = 0; mt < 2; mt++)
#pragma unroll
            for (int pr = 0; pr < 2; pr++) {
                const int row = wm * 32 + mt * 16 + pr * 8 + g;
                float2 v; v.x = acc[mt][nt][pr * 2]; v.y = acc[mt][nt][pr * 2 + 1];
                *reinterpret_cast<float2*>(sT + row * TPITCH + col) = v;
            }
    }
    __syncthreads();

    // coalesced pass: warp -> 8 rows, lane -> 4 contiguous channels
    const int o = colBase + lane * 4;
    const int r0 = warp * 8;

    float4 base4 = *reinterpret_cast<const float4*>(bias + o);
    {
        const float4 ra = *reinterpret_cast<const float4*>(rowA + (size_t)biIdx * HH + o);
        base4.x += ra.x; base4.y += ra.y; base4.z += ra.z; base4.w += ra.w;
    }
    float4 vi4 = make_float4(0.f, 0.f, 0.f, 0.f);
    if (HAS_COL) vi4 = *reinterpret_cast<const float4*>(ViB + (size_t)biIdx * HH + o);

    float4 psum4 = make_float4(0.f, 0.f, 0.f, 0.f);
    float4 psq4  = make_float4(0.f, 0.f, 0.f, 0.f);
    float4 prag4 = make_float4(0.f, 0.f, 0.f, 0.f);

#pragma unroll
    for (int r = 0; r < 8; r++) {
        const int row = r0 + r;
        const size_t nj = bbase + jbase + row;      // b*V + j
        const float4 a = *reinterpret_cast<const float4*>(sT + row * TPITCH + lane * 4);
        const float4 rb = *reinterpret_cast<const float4*>(rowB + nj * HH + o);
        float4 v;
        v.x = a.x + base4.x + rb.x;
        v.y = a.y + base4.y + rb.y;
        v.z = a.z + base4.z + rb.z;
        v.w = a.w + base4.w + rb.w;
        *reinterpret_cast<float4*>(Y + (size_t)(rowBase + row) * HH + o) = v;
        psum4.x += v.x; psum4.y += v.y; psum4.z += v.z; psum4.w += v.w;
        psq4.x += v.x * v.x; psq4.y += v.y * v.y;
        psq4.z += v.z * v.z; psq4.w += v.w * v.w;
        const float g0 = 1.f / (1.f + __expf(-v.x));
        const float g1 = 1.f / (1.f + __expf(-v.y));
        const float g2 = 1.f / (1.f + __expf(-v.z));
        const float g3 = 1.f / (1.f + __expf(-v.w));
        if (HAS_ROW) {
            const float4 vj = *reinterpret_cast<const float4*>(VjB + nj * HH + o);
            prag4.x += g0 * vj.x; prag4.y += g1 * vj.y;
            prag4.z += g2 * vj.z; prag4.w += g3 * vj.w;
        }
        if (HAS_COL) {
            float* p = &accCol[nj * HH + o];
            red2(p,     g0 * vi4.x, g1 * vi4.y);
            red2(p + 2, g2 * vi4.z, g3 * vi4.w);
        }
    }

    // per-column stats: 16 warps share each column -> smem atomics
    {
        const int cc = lane * 4;
        atomicAdd(&s_red[cc],     psum4.x); atomicAdd(&s_red[cc + 1], psum4.y);
        atomicAdd(&s_red[cc + 2], psum4.z); atomicAdd(&s_red[cc + 3], psum4.w);
        atomicAdd(&s_red[128 + cc],     psq4.x); atomicAdd(&s_red[128 + cc + 1], psq4.y);
        atomicAdd(&s_red[128 + cc + 2], psq4.z); atomicAdd(&s_red[128 + cc + 3], psq4.w);
        if (HAS_ROW) {
            atomicAdd(&s_red[256 + cc],     prag4.x); atomicAdd(&s_red[256 + cc + 1], prag4.y);
            atomicAdd(&s_red[256 + cc + 2], prag4.z); atomicAdd(&s_red[256 + cc + 3], prag4.w);
        }
    }
    __syncthreads();
    if (tid < 128) {
        const int oc = colBase + tid;
        atomicAdd(&esum[oc], s_red[tid]);
        atomicAdd(&esq[oc],  s_red[128 + tid]);
        if (HAS_ROW) atomicAdd(&accRow[(size_t)biIdx * HH + oc], s_red[256 + tid]);
    }
}

// ==================================================================
// Node linears (12 small GEMMs) — mma.sync path (tiny cost)
// ==================================================================
__global__ void __launch_bounds__(256) gemm_node(
    const float* __restrict__ Xsc, const float* __restrict__ Xst,
    const float* __restrict__ Wall, const float* __restrict__ ball)
{
    __shared__ uint32_t sA[64 * 32];
    __shared__ uint32_t sB[128 * 32];

    const int job = blockIdx.z;
    const int wsl[12] = {0, 1, 2, 3, 4, 5, 6, 7, 9, 10, 12, 13};
    const bool use_st = (job == 1) || (job == 3) || (job == 5) || (job == 7) ||
                        (job == 10) || (job == 11);
    const float* X = use_st ? Xst : Xsc;
    const float* W = Wall + wsl[job] * HH * HH;
    const float* bias = ball + wsl[job] * HH;
    float* Y = (job == 0) ? g_acc_sc : (job == 1) ? g_acc_st
                          : (g_node + (size_t)(job - 2) * NH);

    const int tid  = threadIdx.x;
    const int lane = tid & 31;
    const int warp = tid >> 5;
    const int wm = warp & 1;
    const int wn = warp >> 1;
    const int g = lane >> 2;
    const int t = lane & 3;
    const int rowBase = blockIdx.y * 64;
    const int colBase = blockIdx.x * 128;

    float acc[2][4][4];
#pragma unroll
    for (int a = 0; a < 2; a++)
#pragma unroll
        for (int b = 0; b < 4; b++)
#pragma unroll
            for (int c = 0; c < 4; c++) acc[a][b][c] = 0.f;

    const int lr = tid >> 3;
    const int lf = tid & 7;

    for (int k0 = 0; k0 < HH; k0 += 32) {
#pragma unroll
        for (int rr = 0; rr < 2; rr++) {
            const int r = lr + rr * 32;
            const float4 v = *reinterpret_cast<const float4*>(
                X + (size_t)(rowBase + r) * HH + k0 + lf * 4);
            uint32_t* p = &sA[r * 32 + ((lf ^ (r & 7)) << 2)];
            p[0] = f2tf(v.x); p[1] = f2tf(v.y); p[2] = f2tf(v.z); p[3] = f2tf(v.w);
        }
#pragma unroll
        for (int rr = 0; rr < 4; rr++) {
            const int n = lr + rr * 32;
            const float4 v = *reinterpret_cast<const float4*>(
                W + (size_t)(colBase + n) * HH + k0 + lf * 4);
            uint32_t* p = &sB[n * 32 + ((lf ^ (n & 7)) << 2)];
            p[0] = f2tf(v.x); p[1] = f2tf(v.y); p[2] = f2tf(v.z); p[3] = f2tf(v.w);
        }
        __syncthreads();

#pragma unroll
        for (int ks = 0; ks < 4; ks++) {
            const int kk = ks * 8;
            uint32_t af[2][4];
#pragma unroll
            for (int mt = 0; mt < 2; mt++) {
                const int r0 = wm * 32 + mt * 16 + g;
                const int sw = (r0 & 7) << 2;
                af[mt][0] = sA[r0 * 32 + ((kk + t) ^ sw)];
                af[mt][1] = sA[(r0 + 8) * 32 + ((kk + t) ^ sw)];
                af[mt][2] = sA[r0 * 32 + ((kk + t + 4) ^ sw)];
                af[mt][3] = sA[(r0 + 8) * 32 + ((kk + t + 4) ^ sw)];
            }
#pragma unroll
            for (int nt = 0; nt < 4; nt++) {
                const int n0 = wn * 32 + nt * 8 + g;
                const int sw = (n0 & 7) << 2;
                uint32_t bf[2];
                bf[0] = sB[n0 * 32 + ((kk + t) ^ sw)];
                bf[1] = sB[n0 * 32 + ((kk + t + 4) ^ sw)];
                mma8(acc[0][nt], af[0], bf);
                mma8(acc[1][nt], af[1], bf);
            }
        }
        __syncthreads();
    }

#pragma unroll
    for (int nt = 0; nt < 4; nt++) {
        const int col = wn * 32 + nt * 8 + t * 2;
        const int o = colBase + col;
        const float b0 = bias[o], b1 = bias[o + 1];
#pragma unroll
        for (int mt = 0; mt < 2; mt++)
#pragma unroll
            for (int pr = 0; pr < 2; pr++) {
                const int row = wm * 32 + mt * 16 + pr * 8 + g;
                float2 v;
                v.x = acc[mt][nt][pr * 2 + 0] + b0;
                v.y = acc[mt][nt][pr * 2 + 1] + b1;
                *reinterpret_cast<float2*>(Y + (size_t)(rowBase + row) * HH + o) = v;
            }
    }
}

// ==================================================================
// BN finalize + output kernels
// ==================================================================
__global__ void k_init() {
    const int i = blockIdx.x * 256 + threadIdx.x;
    if (i < 3 * HH) { g_esum[i] = 0.f; g_esq[i] = 0.f; }
    if (i < 2 * HH) { g_hsum[i] = 0.f; g_hsq[i] = 0.f; }
}

// per-mode BN finalize for edges (narrow dependency for stream overlap)
__global__ void k_edge_stats1(const float* __restrict__ gamma_e,
                              const float* __restrict__ beta_e, int tsel) {
    const int c = threadIdx.x;            // 256 channels
    const int i = tsel * HH + c;
    const float inv = 1.f / (float)REDGE;
    const float mean = g_esum[i] * inv;
    const float var = g_esq[i] * inv - mean * mean;
    const float s = gamma_e[c] * rsqrtf(var + EPS_BN);
    g_escale[i] = s;
    g_eshift[i] = beta_e[c] - mean * s;
}

__global__ void k_hstats() {
    const int t = blockIdx.y;
    const float* a = t ? g_acc_st : g_acc_sc;
    const int c = threadIdx.x;
    const int r0 = blockIdx.x * 64;
    float s = 0.f, q = 0.f;
    for (int k = 0; k < 64; k++) {
        const float v = a[(size_t)(r0 + k) * HH + c];
        s += v; q += v * v;
    }
    atomicAdd(&g_hsum[t * HH + c], s);
    atomicAdd(&g_hsq[t * HH + c], q);
}

__global__ void k_hscale(const float* __restrict__ gamma_h, const float* __restrict__ beta_h) {
    const int i = blockIdx.x * 256 + threadIdx.x;
    if (i < 2 * HH) {
        const int c = i & 255;
        const float inv = 1.f / (float)RN;
        const float mean = g_hsum[i] * inv;
        const float var = g_hsq[i] * inv - mean * mean;
        const float s = gamma_h[c] * rsqrtf(var + EPS_BN);
        g_hscale[i] = s;
        g_hshift[i] = beta_h[c] - mean * s;
    }
}

__global__ void k_hout(const float* __restrict__ hsc, const float* __restrict__ hst,
                       float* __restrict__ out) {
    const int t = blockIdx.y;
    const int i = blockIdx.x * 256 + threadIdx.x;
    const int c = i & 255;
    const float* a = t ? g_acc_st : g_acc_sc;
    const float* hin = t ? hst : hsc;
    const float v = g_hscale[t * HH + c] * a[i] + g_hshift[t * HH + c];
    out[(size_t)t * NH + i] = hin[i] + fmaxf(v, 0.f);
}

__global__ void k_eout(const float* __restrict__ ein, float* __restrict__ eo, int tsel) {
    const int i = blockIdx.x * 256 + threadIdx.x;   // float4 index
    const int c4 = (i & 63) << 2;
    const float4 e2 = reinterpret_cast<const float4*>(eo)[i];
    const float4 ei = reinterpret_cast<const float4*>(ein)[i];
    const float* sc = g_escale + tsel * HH;
    const float* sh = g_eshift + tsel * HH;
    float4 r;
    r.x = ei.x + fmaxf(sc[c4] * e2.x + sh[c4], 0.f);
    r.y = ei.y + fmaxf(sc[c4 + 1] * e2.y + sh[c4 + 1], 0.f);
    r.z = ei.z + fmaxf(sc[c4 + 2] * e2.z + sh[c4 + 2], 0.f);
    r.w = ei.w + fmaxf(sc[c4 + 3] * e2.w + sh[c4 + 3], 0.f);
    reinterpret_cast<float4*>(eo)[i] = r;
}

extern "C" void kernel_launch(void* const* d_in, const int* in_sizes, int n_in,
                              void* d_out, int out_size) {
    const float* h_sc    = (const float*)d_in[0];
    const float* h_st    = (const float*)d_in[1];
    const float* bi_e    = (const float*)d_in[2];
    const float* sc_e    = (const float*)d_in[4];
    const float* st_e    = (const float*)d_in[6];
    const float* Ws      = (const float*)d_in[8];
    const float* bs      = (const float*)d_in[9];
    const float* gamma_h = (const float*)d_in[10];
    const float* beta_h  = (const float*)d_in[11];
    const float* gamma_e = (const float*)d_in[12];
    const float* beta_e  = (const float*)d_in[13];

    float* out = (float*)d_out;
    float* out_bi = out + 2 * (size_t)NH;
    float* out_sc = out_bi + (size_t)REDGE * HH;
    float* out_st = out_sc + (size_t)REDGE * HH;

    cudaFuncSetAttribute(edge_gemm<1>, cudaFuncAttributeMaxDynamicSharedMemorySize, SM_TOTAL);
    cudaFuncSetAttribute(edge_gemm<2>, cudaFuncAttributeMaxDynamicSharedMemorySize, SM_TOTAL);
    cudaFuncSetAttribute(edge_gemm<3>, cudaFuncAttributeMaxDynamicSharedMemorySize, SM_TOTAL);

    // second stream + fork/join events (graph-capturable pattern)
    cudaStream_t s1;
    cudaStreamCreateWithFlags(&s1, cudaStreamNonBlocking);
    cudaEvent_t ev0, ev1, ev2, evj;
    cudaEventCreateWithFlags(&ev0, cudaEventDisableTiming);
    cudaEventCreateWithFlags(&ev1, cudaEventDisableTiming);
    cudaEventCreateWithFlags(&ev2, cudaEventDisableTiming);
    cudaEventCreateWithFlags(&evj, cudaEventDisableTiming);

    k_init<<<3, 256>>>();
    gemm_node<<<dim3(2, 8, 12), 256>>>(h_sc, h_st, Ws, bs);
    edge_gemm<1><<<dim3(2, 1024), 512, SM_TOTAL>>>(bi_e, Ws + 8  * HH * HH, bs + 8  * HH, out_bi);
    cudaEventRecord(ev0, 0);
    edge_gemm<2><<<dim3(2, 1024), 512, SM_TOTAL>>>(sc_e, Ws + 11 * HH * HH, bs + 11 * HH, out_sc);
    cudaEventRecord(ev1, 0);
    edge_gemm<3><<<dim3(2, 1024), 512, SM_TOTAL>>>(st_e, Ws + 14 * HH * HH, bs + 14 * HH, out_st);
    cudaEventRecord(ev2, 0);

    // side stream: per-mode BN finalize + edge output, overlapped with later GEMMs
    cudaStreamWaitEvent(s1, ev0, 0);
    k_edge_stats1<<<1, 256, 0, s1>>>(gamma_e, beta_e, 0);
    k_eout<<<32768, 256, 0, s1>>>(bi_e, out_bi, 0);
    cudaStreamWaitEvent(s1, ev1, 0);
    k_edge_stats1<<<1, 256, 0, s1>>>(gamma_e, beta_e, 1);
    k_eout<<<32768, 256, 0, s1>>>(sc_e, out_sc, 1);
    cudaStreamWaitEvent(s1, ev2, 0);
    k_edge_stats1<<<1, 256, 0, s1>>>(gamma_e, beta_e, 2);
    k_eout<<<32768, 256, 0, s1>>>(st_e, out_st, 2);
    cudaEventRecord(evj, s1);

    // node-side finalize on main stream (depends only on edge gemms)
    k_hstats<<<dim3(8, 2), 256>>>();
    k_hscale<<<2, 256>>>(gamma_h, beta_h);
    k_hout<<<dim3(512, 2), 256>>>(h_sc, h_st, out);

    // join side stream back into the capture origin stream
    cudaStreamWaitEvent(0, evj, 0);
}

// round 13
// speedup vs baseline: 1.0851x; 1.0851x over previous
#include <cuda_runtime.h>
#include <math.h>
#include <stdint.h>

#define HH 256
#define RN 512                 // B*V node rows
#define NH (RN*HH)             // node tensor elements
#define REDGE 131072           // B*V*V edge rows
#define EPS_BN 1e-5f

// node scratch slots
#define N_VSC 0
#define N_VST 1
#define N_WSC 2
#define N_WST 3
#define N_ABI 4
#define N_BBI 5
#define N_ASC 6
#define N_BSC 7
#define N_AST 8
#define N_BST 9

__device__ float g_node[10 * NH];
__device__ float g_acc_sc[NH];   // starts as Uh_sc, atomically accumulated
__device__ float g_acc_st[NH];   // starts as Uh_st
__device__ float g_esum[3 * HH];
__device__ float g_esq[3 * HH];
__device__ float g_escale[3 * HH];
__device__ float g_eshift[3 * HH];
__device__ float g_hsum[2 * HH];
__device__ float g_hsq[2 * HH];
__device__ float g_hscale[2 * HH];
__device__ float g_hshift[2 * HH];

// ------------------------------------------------------------------
// helpers
// ------------------------------------------------------------------
__device__ __forceinline__ uint32_t f2tf(float f) {
    uint32_t u;
    asm("cvt.rna.tf32.f32 %0, %1;" : "=r"(u) : "f"(f));
    return u;
}

__device__ __forceinline__ uint32_t smem_u32(const void* p) {
    uint32_t a;
    asm("{ .reg .u64 t; cvta.to.shared.u64 t, %1; cvt.u32.u64 %0, t; }"
        : "=r"(a) : "l"(p));
    return a;
}

__device__ __forceinline__ void cpa16(uint32_t dst, const void* src) {
    asm volatile("cp.async.cg.shared.global [%0], [%1], 16;"
                 :: "r"(dst), "l"(src) : "memory");
}
__device__ __forceinline__ void cpa_commit() {
    asm volatile("cp.async.commit_group;" ::: "memory");
}
template <int N>
__device__ __forceinline__ void cpa_wait() {
    asm volatile("cp.async.wait_group %0;" :: "n"(N) : "memory");
}

__device__ __forceinline__ void red2(float* p, float a, float b) {
    asm volatile("red.global.add.v2.f32 [%0], {%1, %2};"
                 :: "l"(p), "f"(a), "f"(b) : "memory");
}

__device__ __forceinline__ void mma8(float* d, const uint32_t* a, const uint32_t* b) {
    asm volatile(
        "mma.sync.aligned.m16n8k8.row.col.f32.tf32.tf32.f32 "
        "{%0,%1,%2,%3},{%4,%5,%6,%7},{%8,%9},{%0,%1,%2,%3};"
        : "+f"(d[0]), "+f"(d[1]), "+f"(d[2]), "+f"(d[3])
        : "r"(a[0]), "r"(a[1]), "r"(a[2]), "r"(a[3]), "r"(b[0]), "r"(b[1]));
}

__device__ __forceinline__ void ldsm4(uint32_t& r0, uint32_t& r1, uint32_t& r2,
                                      uint32_t& r3, uint32_t addr) {
    asm volatile("ldmatrix.sync.aligned.m8n8.x4.shared.b16 {%0,%1,%2,%3}, [%4];"
                 : "=r"(r0), "=r"(r1), "=r"(r2), "=r"(r3) : "r"(addr));
}

// ==================================================================
// Edge GEMM: e2[row, ch] = X[row,:]·W[ch,:] + bias + Ah_i + Bh_j, fused
// sigmoid-gate aggregation + BN statistics.
// CTA tile: 128 rows x 128 channels, K=256 in 8 chunks of 32.
// 8 warps (2M x 4N), warp tile 64x32. 3-stage cp.async pipeline,
// ldmatrix fragment loads, raw fp32 bits into tf32 mma (RZ).
// Epilogue is fully coalesced via an smem accumulator transpose.
// MODE: 1 = bi edge, 2 = sc edge, 3 = st edge
// ==================================================================
#define SM_CHUNK 16384                 // one operand tile: 128 rows * 128B
#define SM_BUF   (2 * SM_CHUNK)        // A + B tiles per stage (32KB)
#define SM_TOTAL (3 * SM_BUF)          // 3 stages = 96KB
#define TPITCH   132                   // padded fp32 pitch for transpose
#define SRED_OFF (128 * TPITCH)        // float offset of stats scratch

template <int MODE>
__global__ void __launch_bounds__(256, 2) edge_gemm(
    const float* __restrict__ X, const float* __restrict__ W,
    const float* __restrict__ bias, float* __restrict__ Y)
{
    extern __shared__ char smem[];
    const uint32_t sbase = smem_u32(smem);

    const int tid  = threadIdx.x;
    const int lane = tid & 31;
    const int warp = tid >> 5;
    const int wm = warp & 1;       // 2 warps along M (64 rows each)
    const int wn = warp >> 1;      // 4 warps along N (32 cols each)
    const int g = lane >> 2;
    const int t = lane & 3;
    const int rowBase = blockIdx.y * 128;
    const int colBase = blockIdx.x * 128;

    const int lr = tid >> 3;       // 0..31
    const int lf = tid & 7;        // float4 index within 32-float k-row

    // ldmatrix per-thread addressing invariants
    const int mlo = (lane >> 3) & 1;   // matrix pair low bit
    const int mhi = lane >> 4;         // matrix pair high bit
    const int rl  = lane & 7;          // row within matrix

    uint32_t aoffm[4]; int a7[4];
#pragma unroll
    for (int mt = 0; mt < 4; mt++) {
        const int row = wm * 64 + mt * 16 + mlo * 8 + rl;
        aoffm[mt] = (uint32_t)row * 128;
        a7[mt] = row & 7;
    }
    uint32_t boffm[2]; int b7[2];
#pragma unroll
    for (int ntp = 0; ntp < 2; ntp++) {
        const int nrow = wn * 32 + (2 * ntp + mhi) * 8 + rl;
        boffm[ntp] = (uint32_t)(SM_CHUNK + nrow * 128);
        b7[ntp] = nrow & 7;
    }

    float acc[4][4][4];
#pragma unroll
    for (int a = 0; a < 4; a++)
#pragma unroll
        for (int b = 0; b < 4; b++)
#pragma unroll
            for (int c = 0; c < 4; c++) acc[a][b][c] = 0.f;

    // ---- staging helper (cp.async, swizzled 16B) ----
    auto stage = [&](int buf, int k0) {
        const uint32_t boff = sbase + buf * SM_BUF;
#pragma unroll
        for (int ii = 0; ii < 4; ii++) {
            const int r = lr + 32 * ii;
            const uint32_t sw = (uint32_t)((lf ^ (r & 7)) << 4);
            cpa16(boff + r * 128 + sw,
                  X + (size_t)(rowBase + r) * HH + k0 + lf * 4);
            cpa16(boff + SM_CHUNK + r * 128 + sw,
                  W + (size_t)(colBase + r) * HH + k0 + lf * 4);
        }
    };

    stage(0, 0);  cpa_commit();
    stage(1, 32); cpa_commit();

    for (int c = 0; c < 8; c++) {
        if (c < 7) cpa_wait<1>(); else cpa_wait<0>();
        __syncthreads();
        if (c < 6) { stage((c + 2) % 3, (c + 2) * 32); cpa_commit(); }

        const uint32_t sb = sbase + (c % 3) * SM_BUF;

#pragma unroll
        for (int ks = 0; ks < 4; ks++) {
            uint32_t af[4][4];
#pragma unroll
            for (int mt = 0; mt < 4; mt++) {
                const uint32_t addr = sb + aoffm[mt] +
                    (uint32_t)(((2 * ks + mhi) ^ a7[mt]) << 4);
                ldsm4(af[mt][0], af[mt][1], af[mt][2], af[mt][3], addr);
            }
            uint32_t bf[2][4];
#pragma unroll
            for (int ntp = 0; ntp < 2; ntp++) {
                const uint32_t addr = sb + boffm[ntp] +
                    (uint32_t)(((2 * ks + mlo) ^ b7[ntp]) << 4);
                ldsm4(bf[ntp][0], bf[ntp][1], bf[ntp][2], bf[ntp][3], addr);
            }
#pragma unroll
            for (int ntp = 0; ntp < 2; ntp++)
#pragma unroll
                for (int mt = 0; mt < 4; mt++) {
                    mma8(acc[mt][2 * ntp],     af[mt], &bf[ntp][0]);
                    mma8(acc[mt][2 * ntp + 1], af[mt], &bf[ntp][2]);
                }
        }
    }
    __syncthreads();   // mainloop smem no longer needed

    // ---------------- fused epilogue (coalesced via smem transpose) ----------
    constexpr bool HAS_ROW = (MODE == 1) || (MODE == 2);  // sum over j -> acc[b,i]
    constexpr bool HAS_COL = (MODE == 1) || (MODE == 3);  // sum over i -> acc[b,j]

    const float* rowA; const float* rowB;
    const float* VjB = nullptr; const float* ViB = nullptr;
    float* accRow = nullptr; float* accCol = nullptr;
    float* esum; float* esq;
    if (MODE == 1) {
        rowA = g_node + (size_t)N_ABI * NH; rowB = g_node + (size_t)N_BBI * NH;
        VjB = g_node + (size_t)N_VST * NH;  ViB = g_node + (size_t)N_VSC * NH;
        accRow = g_acc_sc; accCol = g_acc_st;
        esum = g_esum; esq = g_esq;
    } else if (MODE == 2) {
        rowA = g_node + (size_t)N_ASC * NH; rowB = g_node + (size_t)N_BSC * NH;
        VjB = g_node + (size_t)N_WSC * NH;
        accRow = g_acc_sc;
        esum = g_esum + HH; esq = g_esq + HH;
    } else {
        rowA = g_node + (size_t)N_AST * NH; rowB = g_node + (size_t)N_BST * NH;
        ViB = g_node + (size_t)N_WST * NH;
        accCol = g_acc_st;
        esum = g_esum + 2 * HH; esq = g_esq + 2 * HH;
    }

    const int biIdx = rowBase >> 8;         // b*V + i (128-row block sits in one i)
    const int bbase = (rowBase >> 16) << 8; // b*V
    const int jbase = rowBase & 255;

    float* sT = reinterpret_cast<float*>(smem);          // [128][TPITCH]
    float* s_red = sT + SRED_OFF;                        // 384 floats

    // dump accumulators to smem (mma layout) + zero stats scratch
    for (int i = tid; i < 384; i += 256) s_red[i] = 0.f;
#pragma unroll
    for (int nt = 0; nt < 4; nt++) {
        const int col = wn * 32 + nt * 8 + t * 2;
#pragma unroll
        for (int mt = 0; mt < 4; mt++)
#pragma unroll
            for (int pr = 0; pr < 2; pr++) {
                const int row = wm * 64 + mt * 16 + pr * 8 + g;
                float2 v; v.x = acc[mt][nt][pr * 2]; v.y = acc[mt][nt][pr * 2 + 1];
                *reinterpret_cast<float2*>(sT + row * TPITCH + col) = v;
            }
    }
    __syncthreads();

    // coalesced pass: warp -> 16 rows, lane -> 4 contiguous channels
    const int o = colBase + lane * 4;
    const int r0 = warp * 16;

    float4 base4 = *reinterpret_cast<const float4*>(bias + o);
    {
        const float4 ra = *reinterpret_cast<const float4*>(rowA + (size_t)biIdx * HH + o);
        base4.x += ra.x; base4.y += ra.y; base4.z += ra.z; base4.w += ra.w;
    }
    float4 vi4 = make_float4(0.f, 0.f, 0.f, 0.f);
    if (HAS_COL) vi4 = *reinterpret_cast<const float4*>(ViB + (size_t)biIdx * HH + o);

    float4 psum4 = make_float4(0.f, 0.f, 0.f, 0.f);
    float4 psq4  = make_float4(0.f, 0.f, 0.f, 0.f);
    float4 prag4 = make_float4(0.f, 0.f, 0.f, 0.f);

#pragma unroll
    for (int r = 0; r < 16; r++) {
        const int row = r0 + r;
        const size_t nj = bbase + jbase + row;      // b*V + j
        const float4 a = *reinterpret_cast<const float4*>(sT + row * TPITCH + lane * 4);
        const float4 rb = *reinterpret_cast<const float4*>(rowB + nj * HH + o);
        float4 v;
        v.x = a.x + base4.x + rb.x;
        v.y = a.y + base4.y + rb.y;
        v.z = a.z + base4.z + rb.z;
        v.w = a.w + base4.w + rb.w;
        *reinterpret_cast<float4*>(Y + (size_t)(rowBase + row) * HH + o) = v;
        psum4.x += v.x; psum4.y += v.y; psum4.z += v.z; psum4.w += v.w;
        psq4.x += v.x * v.x; psq4.y += v.y * v.y;
        psq4.z += v.z * v.z; psq4.w += v.w * v.w;
        const float g0 = 1.f / (1.f + __expf(-v.x));
        const float g1 = 1.f / (1.f + __expf(-v.y));
        const float g2 = 1.f / (1.f + __expf(-v.z));
        const float g3 = 1.f / (1.f + __expf(-v.w));
        if (HAS_ROW) {
            const float4 vj = *reinterpret_cast<const float4*>(VjB + nj * HH + o);
            prag4.x += g0 * vj.x; prag4.y += g1 * vj.y;
            prag4.z += g2 * vj.z; prag4.w += g3 * vj.w;
        }
        if (HAS_COL) {
            float* p = &accCol[nj * HH + o];
            red2(p,     g0 * vi4.x, g1 * vi4.y);
            red2(p + 2, g2 * vi4.z, g3 * vi4.w);
        }
    }

    // per-column stats: 8 warps share each column -> smem atomics
    {
        const int cc = lane * 4;
        atomicAdd(&s_red[cc],     psum4.x); atomicAdd(&s_red[cc + 1], psum4.y);
        atomicAdd(&s_red[cc + 2], psum4.z); atomicAdd(&s_red[cc + 3], psum4.w);
        atomicAdd(&s_red[128 + cc],     psq4.x); atomicAdd(&s_red[128 + cc + 1], psq4.y);
        atomicAdd(&s_red[128 + cc + 2], psq4.z); atomicAdd(&s_red[128 + cc + 3], psq4.w);
        if (HAS_ROW) {
            atomicAdd(&s_red[256 + cc],     prag4.x); atomicAdd(&s_red[256 + cc + 1], prag4.y);
            atomicAdd(&s_red[256 + cc + 2], prag4.z); atomicAdd(&s_red[256 + cc + 3], prag4.w);
        }
    }
    __syncthreads();
    if (tid < 128) {
        const int oc = colBase + tid;
        atomicAdd(&esum[oc], s_red[tid]);
        atomicAdd(&esq[oc],  s_red[128 + tid]);
        if (HAS_ROW) atomicAdd(&accRow[(size_t)biIdx * HH + oc], s_red[256 + tid]);
    }
}

// ==================================================================
// Node linears (12 small GEMMs) — mma.sync path (tiny cost)
// ==================================================================
__global__ void __launch_bounds__(256) gemm_node(
    const float* __restrict__ Xsc, const float* __restrict__ Xst,
    const float* __restrict__ Wall, const float* __restrict__ ball)
{
    __shared__ uint32_t sA[64 * 32];
    __shared__ uint32_t sB[128 * 32];

    const int job = blockIdx.z;
    const int wsl[12] = {0, 1, 2, 3, 4, 5, 6, 7, 9, 10, 12, 13};
    const bool use_st = (job == 1) || (job == 3) || (job == 5) || (job == 7) ||
                        (job == 10) || (job == 11);
    const float* X = use_st ? Xst : Xsc;
    const float* W = Wall + wsl[job] * HH * HH;
    const float* bias = ball + wsl[job] * HH;
    float* Y = (job == 0) ? g_acc_sc : (job == 1) ? g_acc_st
                          : (g_node + (size_t)(job - 2) * NH);

    const int tid  = threadIdx.x;
    const int lane = tid & 31;
    const int warp = tid >> 5;
    const int wm = warp & 1;
    const int wn = warp >> 1;
    const int g = lane >> 2;
    const int t = lane & 3;
    const int rowBase = blockIdx.y * 64;
    const int colBase = blockIdx.x * 128;

    float acc[2][4][4];
#pragma unroll
    for (int a = 0; a < 2; a++)
#pragma unroll
        for (int b = 0; b < 4; b++)
#pragma unroll
            for (int c = 0; c < 4; c++) acc[a][b][c] = 0.f;

    const int lr = tid >> 3;
    const int lf = tid & 7;

    for (int k0 = 0; k0 < HH; k0 += 32) {
#pragma unroll
        for (int rr = 0; rr < 2; rr++) {
            const int r = lr + rr * 32;
            const float4 v = *reinterpret_cast<const float4*>(
                X + (size_t)(rowBase + r) * HH + k0 + lf * 4);
            uint32_t* p = &sA[r * 32 + ((lf ^ (r & 7)) << 2)];
            p[0] = f2tf(v.x); p[1] = f2tf(v.y); p[2] = f2tf(v.z); p[3] = f2tf(v.w);
        }
#pragma unroll
        for (int rr = 0; rr < 4; rr++) {
            const int n = lr + rr * 32;
            const float4 v = *reinterpret_cast<const float4*>(
                W + (size_t)(colBase + n) * HH + k0 + lf * 4);
            uint32_t* p = &sB[n * 32 + ((lf ^ (n & 7)) << 2)];
            p[0] = f2tf(v.x); p[1] = f2tf(v.y); p[2] = f2tf(v.z); p[3] = f2tf(v.w);
        }
        __syncthreads();

#pragma unroll
        for (int ks = 0; ks < 4; ks++) {
            const int kk = ks * 8;
            uint32_t af[2][4];
#pragma unroll
            for (int mt = 0; mt < 2; mt++) {
                const int r0 = wm * 32 + mt * 16 + g;
                const int sw = (r0 & 7) << 2;
                af[mt][0] = sA[r0 * 32 + ((kk + t) ^ sw)];
                af[mt][1] = sA[(r0 + 8) * 32 + ((kk + t) ^ sw)];
                af[mt][2] = sA[r0 * 32 + ((kk + t + 4) ^ sw)];
                af[mt][3] = sA[(r0 + 8) * 32 + ((kk + t + 4) ^ sw)];
            }
#pragma unroll
            for (int nt = 0; nt < 4; nt++) {
                const int n0 = wn * 32 + nt * 8 + g;
                const int sw = (n0 & 7) << 2;
                uint32_t bf[2];
                bf[0] = sB[n0 * 32 + ((kk + t) ^ sw)];
                bf[1] = sB[n0 * 32 + ((kk + t + 4) ^ sw)];
                mma8(acc[0][nt], af[0], bf);
                mma8(acc[1][nt], af[1], bf);
            }
        }
        __syncthreads();
    }

#pragma unroll
    for (int nt = 0; nt < 4; nt++) {
        const int col = wn * 32 + nt * 8 + t * 2;
        const int o = colBase + col;
        const float b0 = bias[o], b1 = bias[o + 1];
#pragma unroll
        for (int mt = 0; mt < 2; mt++)
#pragma unroll
            for (int pr = 0; pr < 2; pr++) {
                const int row = wm * 32 + mt * 16 + pr * 8 + g;
                float2 v;
                v.x = acc[mt][nt][pr * 2 + 0] + b0;
                v.y = acc[mt][nt][pr * 2 + 1] + b1;
                *reinterpret_cast<float2*>(Y + (size_t)(rowBase + row) * HH + o) = v;
            }
    }
}

// ==================================================================
// BN finalize + output kernels
// ==================================================================
__global__ void k_init() {
    const int i = blockIdx.x * 256 + threadIdx.x;
    if (i < 3 * HH) { g_esum[i] = 0.f; g_esq[i] = 0.f; }
    if (i < 2 * HH) { g_hsum[i] = 0.f; g_hsq[i] = 0.f; }
}

// per-mode BN finalize for edges (narrow dependency for stream overlap)
__global__ void k_edge_stats1(const float* __restrict__ gamma_e,
                              const float* __restrict__ beta_e, int tsel) {
    const int c = threadIdx.x;            // 256 channels
    const int i = tsel * HH + c;
    const float inv = 1.f / (float)REDGE;
    const float mean = g_esum[i] * inv;
    const float var = g_esq[i] * inv - mean * mean;
    const float s = gamma_e[c] * rsqrtf(var + EPS_BN);
    g_escale[i] = s;
    g_eshift[i] = beta_e[c] - mean * s;
}

__global__ void k_hstats() {
    const int t = blockIdx.y;
    const float* a = t ? g_acc_st : g_acc_sc;
    const int c = threadIdx.x;
    const int r0 = blockIdx.x * 64;
    float s = 0.f, q = 0.f;
    for (int k = 0; k < 64; k++) {
        const float v = a[(size_t)(r0 + k) * HH + c];
        s += v; q += v * v;
    }
    atomicAdd(&g_hsum[t * HH + c], s);
    atomicAdd(&g_hsq[t * HH + c], q);
}

__global__ void k_hscale(const float* __restrict__ gamma_h, const float* __restrict__ beta_h) {
    const int i = blockIdx.x * 256 + threadIdx.x;
    if (i < 2 * HH) {
        const int c = i & 255;
        const float inv = 1.f / (float)RN;
        const float mean = g_hsum[i] * inv;
        const float var = g_hsq[i] * inv - mean * mean;
        const float s = gamma_h[c] * rsqrtf(var + EPS_BN);
        g_hscale[i] = s;
        g_hshift[i] = beta_h[c] - mean * s;
    }
}

__global__ void k_hout(const float* __restrict__ hsc, const float* __restrict__ hst,
                       float* __restrict__ out) {
    const int t = blockIdx.y;
    const int i = blockIdx.x * 256 + threadIdx.x;
    const int c = i & 255;
    const float* a = t ? g_acc_st : g_acc_sc;
    const float* hin = t ? hst : hsc;
    const float v = g_hscale[t * HH + c] * a[i] + g_hshift[t * HH + c];
    out[(size_t)t * NH + i] = hin[i] + fmaxf(v, 0.f);
}

__global__ void k_eout(const float* __restrict__ ein, float* __restrict__ eo, int tsel) {
    const int i = blockIdx.x * 256 + threadIdx.x;   // float4 index
    const int c4 = (i & 63) << 2;
    const float4 e2 = reinterpret_cast<const float4*>(eo)[i];
    const float4 ei = reinterpret_cast<const float4*>(ein)[i];
    const float* sc = g_escale + tsel * HH;
    const float* sh = g_eshift + tsel * HH;
    float4 r;
    r.x = ei.x + fmaxf(sc[c4] * e2.x + sh[c4], 0.f);
    r.y = ei.y + fmaxf(sc[c4 + 1] * e2.y + sh[c4 + 1], 0.f);
    r.z = ei.z + fmaxf(sc[c4 + 2] * e2.z + sh[c4 + 2], 0.f);
    r.w = ei.w + fmaxf(sc[c4 + 3] * e2.w + sh[c4 + 3], 0.f);
    reinterpret_cast<float4*>(eo)[i] = r;
}

extern "C" void kernel_launch(void* const* d_in, const int* in_sizes, int n_in,
                              void* d_out, int out_size) {
    const float* h_sc    = (const float*)d_in[0];
    const float* h_st    = (const float*)d_in[1];
    const float* bi_e    = (const float*)d_in[2];
    const float* sc_e    = (const float*)d_in[4];
    const float* st_e    = (const float*)d_in[6];
    const float* Ws      = (const float*)d_in[8];
    const float* bs      = (const float*)d_in[9];
    const float* gamma_h = (const float*)d_in[10];
    const float* beta_h  = (const float*)d_in[11];
    const float* gamma_e = (const float*)d_in[12];
    const float* beta_e  = (const float*)d_in[13];

    float* out = (float*)d_out;
    float* out_bi = out + 2 * (size_t)NH;
    float* out_sc = out_bi + (size_t)REDGE * HH;
    float* out_st = out_sc + (size_t)REDGE * HH;

    cudaFuncSetAttribute(edge_gemm<1>, cudaFuncAttributeMaxDynamicSharedMemorySize, SM_TOTAL);
    cudaFuncSetAttribute(edge_gemm<2>, cudaFuncAttributeMaxDynamicSharedMemorySize, SM_TOTAL);
    cudaFuncSetAttribute(edge_gemm<3>, cudaFuncAttributeMaxDynamicSharedMemorySize, SM_TOTAL);

    // ONE side stream (proven teardown-clean budget) + 5 events
    cudaStream_t s1;
    cudaStreamCreateWithFlags(&s1, cudaStreamNonBlocking);
    cudaEvent_t evn, evg1, evg2, evg3, evj;
    cudaEventCreateWithFlags(&evn, cudaEventDisableTiming);
    cudaEventCreateWithFlags(&evg1, cudaEventDisableTiming);
    cudaEventCreateWithFlags(&evg2, cudaEventDisableTiming);
    cudaEventCreateWithFlags(&evg3, cudaEventDisableTiming);
    cudaEventCreateWithFlags(&evj, cudaEventDisableTiming);

    k_init<<<3, 256>>>();
    gemm_node<<<dim3(2, 8, 12), 256>>>(h_sc, h_st, Ws, bs);
    cudaEventRecord(evn, 0);
    cudaStreamWaitEvent(s1, evn, 0);

    // eg2 on side stream, concurrent with eg1 -> eg3 on origin
    edge_gemm<2><<<dim3(2, 1024), 256, SM_TOTAL, s1>>>(sc_e, Ws + 11 * HH * HH, bs + 11 * HH, out_sc);
    cudaEventRecord(evg2, s1);
    edge_gemm<1><<<dim3(2, 1024), 256, SM_TOTAL>>>(bi_e, Ws + 8  * HH * HH, bs + 8  * HH, out_bi);
    cudaEventRecord(evg1, 0);
    edge_gemm<3><<<dim3(2, 1024), 256, SM_TOTAL>>>(st_e, Ws + 14 * HH * HH, bs + 14 * HH, out_st);
    cudaEventRecord(evg3, 0);

    // side stream: mode sc finalize, then bi (after evg1), then st (after evg3)
    k_edge_stats1<<<1, 256, 0, s1>>>(gamma_e, beta_e, 1);
    k_eout<<<32768, 256, 0, s1>>>(sc_e, out_sc, 1);
    cudaStreamWaitEvent(s1, evg1, 0);
    k_edge_stats1<<<1, 256, 0, s1>>>(gamma_e, beta_e, 0);
    k_eout<<<32768, 256, 0, s1>>>(bi_e, out_bi, 0);
    cudaStreamWaitEvent(s1, evg3, 0);
    k_edge_stats1<<<1, 256, 0, s1>>>(gamma_e, beta_e, 2);
    k_eout<<<32768, 256, 0, s1>>>(st_e, out_st, 2);
    cudaEventRecord(evj, s1);

    // node-side finalize on origin: eg1/eg3 ordered here; wait eg2's atomics
    cudaStreamWaitEvent(0, evg2, 0);
    k_hstats<<<dim3(8, 2), 256>>>();
    k_hscale<<<2, 256>>>(gamma_h, beta_h);
    k_hout<<<dim3(512, 2), 256>>>(h_sc, h_st, out);

    // join side stream back into the capture origin stream
    cudaStreamWaitEvent(0, evj, 0);
}